// round 4
// baseline (speedup 1.0000x reference)
#include <cuda_runtime.h>
#include <math.h>

// Problem constants
#define BB 128      // batch
#define TT 128      // time steps
#define FF 128      // features
#define DD 512      // hidden
#define NG 2048     // 4*D
#define KC 32       // K-chunk

// Scratch (device globals — no allocation allowed)
__device__ float g_h [BB*DD];
__device__ float g_c [BB*DD];
__device__ float g_h0[BB*DD];
__device__ float g_c0[BB*DD];
__device__ float g_hA[BB*DD];
__device__ float g_cA[BB*DD];
__device__ float g_hB[BB*DD];
__device__ float g_cB[BB*DD];
__device__ float g_Wsum[DD*NG];

__device__ __forceinline__ float sigmoidf_(float x) { return 1.0f / (1.0f + expf(-x)); }

// Wsum = enc_W1 + enc_U1  (valid because encoder layer 1 has x == h)
__global__ void add_mats_kernel(const float* __restrict__ a, const float* __restrict__ b,
                                float* __restrict__ o, int n) {
    int i = blockIdx.x * blockDim.x + threadIdx.x;
    if (i < n) o[i] = a[i] + b[i];
}

// Fused LSTM cell: z = X@W (K1 cols, row stride ldx) + H@U (K2 cols) + bias,
// then i,f,o = sigmoid; g = relu; c2 = f*cin + i*g; h2 = o*relu(c2).
//
// Grid: 128 blocks; block owns 4 D-columns (all 4 gates of each).
// 256 threads: thread (q = tid>>2, c = tid&3) computes rows {2q, 2q+1} x col c x 4 gates.
// As[k][row] (transposed)  -> thread's 2 rows via one LDS.64 (warp: 64B distinct, bcast x4).
// Bs[k][c*4+g]             -> thread's 4 gates via one LDS.128 (warp: 64B distinct, bcast x8).
// Register prefetch of the NEXT K-chunk overlaps LDG latency with FFMA work.
__global__ __launch_bounds__(256, 1) void lstm_cell_kernel(
    const float* __restrict__ X, int ldx, int K1, const float* __restrict__ W,
    const float* __restrict__ H, const float* __restrict__ U, int K2,
    const float* __restrict__ bias, const float* __restrict__ cin,
    float* __restrict__ hout, float* __restrict__ cout)
{
    __shared__ float As[KC][BB];      // 16 KB, [k][row]
    __shared__ float Bs[KC][16];      // 2 KB,  [k][c*4 + gate]

    const int tid = threadIdx.x;
    const int jb  = blockIdx.x * 4;          // D-column base
    const int q   = tid >> 2;                // row group 0..63
    const int c   = tid & 3;                 // col within block

    // staging roles
    const int ar  = tid & 127;               // A row this thread stages
    const int akb = (tid >> 7) * 16;         // A k-offset base (0 or 16)
    const int bkk = tid >> 3;                // B k-row (0..31)
    const int bm  = (tid & 7) * 2;           // z-col pair index (even)
    const int bg  = bm >> 2;                 // gate 0..3
    const int bc  = bm & 3;                  // col 0 or 2 (pair bc, bc+1 same gate)

    const int totK = K1 + K2;

    float pa[16];
    float pb0, pb1;

    // prefetch chunk 0 (k0 = 0 always lies in phase-1 since K1 >= KC)
    {
        #pragma unroll
        for (int p = 0; p < 4; ++p) {
            float4 v = *(const float4*)(X + (size_t)ar * ldx + akb + p * 4);
            pa[p*4+0] = v.x; pa[p*4+1] = v.y; pa[p*4+2] = v.z; pa[p*4+3] = v.w;
        }
        const float* src = W + (size_t)bkk * NG + bg * DD + jb + bc;
        pb0 = src[0]; pb1 = src[1];
    }

    float acc00 = 0.f, acc01 = 0.f, acc02 = 0.f, acc03 = 0.f;
    float acc10 = 0.f, acc11 = 0.f, acc12 = 0.f, acc13 = 0.f;

    for (int k0 = 0; k0 < totK; k0 += KC) {
        __syncthreads();
        // commit staged registers to smem
        #pragma unroll
        for (int p = 0; p < 16; ++p) As[akb + p][ar] = pa[p];
        Bs[bkk][bc * 4 + bg]       = pb0;
        Bs[bkk][(bc + 1) * 4 + bg] = pb1;
        __syncthreads();

        // issue LDGs for the next chunk (latency hidden by compute below)
        int kn = k0 + KC;
        if (kn < totK) {
            const float* Ap; int lda; int kA;
            if (kn < K1) { Ap = X; lda = ldx; kA = kn; }
            else         { Ap = H; lda = DD;  kA = kn - K1; }
            #pragma unroll
            for (int p = 0; p < 4; ++p) {
                float4 v = *(const float4*)(Ap + (size_t)ar * lda + kA + akb + p * 4);
                pa[p*4+0] = v.x; pa[p*4+1] = v.y; pa[p*4+2] = v.z; pa[p*4+3] = v.w;
            }
            const float* Bp; int kB;
            if (kn < K1) { Bp = W; kB = kn; } else { Bp = U; kB = kn - K1; }
            const float* src = Bp + (size_t)(kB + bkk) * NG + bg * DD + jb + bc;
            pb0 = src[0]; pb1 = src[1];
        }

        // FFMA core: 8 FMA + 2 LDS per k per thread
        #pragma unroll
        for (int kk = 0; kk < KC; ++kk) {
            float2 a = *(const float2*)&As[kk][2 * q];
            float4 b = *(const float4*)&Bs[kk][c * 4];
            acc00 += a.x * b.x; acc01 += a.x * b.y; acc02 += a.x * b.z; acc03 += a.x * b.w;
            acc10 += a.y * b.x; acc11 += a.y * b.y; acc12 += a.y * b.z; acc13 += a.y * b.w;
        }
    }

    const int col = jb + c;
    const float bi  = bias[col];
    const float bf  = bias[DD + col];
    const float bgg = bias[2 * DD + col];
    const float bo  = bias[3 * DD + col];

    {
        int r = 2 * q;
        float i = sigmoidf_(acc00 + bi);
        float f = sigmoidf_(acc01 + bf);
        float g = fmaxf(acc02 + bgg, 0.f);
        float o = sigmoidf_(acc03 + bo);
        float c2 = f * cin[r * DD + col] + i * g;
        cout[r * DD + col] = c2;
        hout[r * DD + col] = o * fmaxf(c2, 0.f);
    }
    {
        int r = 2 * q + 1;
        float i = sigmoidf_(acc10 + bi);
        float f = sigmoidf_(acc11 + bf);
        float g = fmaxf(acc12 + bgg, 0.f);
        float o = sigmoidf_(acc13 + bo);
        float c2 = f * cin[r * DD + col] + i * g;
        cout[r * DD + col] = c2;
        hout[r * DD + col] = o * fmaxf(c2, 0.f);
    }
}

// out[b, col] = H[b,:] @ Wd[:,col] + bd[col]; one block per batch row.
// Wd reads are perfectly coalesced (128 consecutive floats per k).
__global__ __launch_bounds__(128, 1) void dense_kernel(
    const float* __restrict__ H, const float* __restrict__ Wd,
    const float* __restrict__ bd, float* __restrict__ out)
{
    __shared__ float hs[DD];
    const int row = blockIdx.x;
    const int col = threadIdx.x;
    const float* h = H + (size_t)row * DD;
    #pragma unroll
    for (int k = col; k < DD; k += 128) hs[k] = h[k];
    __syncthreads();
    float a0 = 0.f, a1 = 0.f, a2 = 0.f, a3 = 0.f;
    #pragma unroll 4
    for (int k = 0; k < DD; k += 4) {
        a0 += hs[k + 0] * Wd[(size_t)(k + 0) * FF + col];
        a1 += hs[k + 1] * Wd[(size_t)(k + 1) * FF + col];
        a2 += hs[k + 2] * Wd[(size_t)(k + 2) * FF + col];
        a3 += hs[k + 3] * Wd[(size_t)(k + 3) * FF + col];
    }
    out[(size_t)row * TT * FF + col] = (a0 + a1) + (a2 + a3) + bd[col];
}

extern "C" void kernel_launch(void* const* d_in, const int* in_sizes, int n_in,
                              void* d_out, int out_size)
{
    const float* enc_in  = (const float*)d_in[0];
    const float* dec_in  = (const float*)d_in[1];
    const float* enc_W0  = (const float*)d_in[2];
    const float* enc_U0  = (const float*)d_in[3];
    const float* enc_b0  = (const float*)d_in[4];
    const float* enc_W1  = (const float*)d_in[5];
    const float* enc_U1  = (const float*)d_in[6];
    const float* enc_b1  = (const float*)d_in[7];
    const float* dec_W0  = (const float*)d_in[8];
    const float* dec_U0  = (const float*)d_in[9];
    const float* dec_b0  = (const float*)d_in[10];
    const float* dec_W1  = (const float*)d_in[11];
    const float* dec_U1  = (const float*)d_in[12];
    const float* dec_b1  = (const float*)d_in[13];
    const float* dense_W = (const float*)d_in[14];
    const float* dense_b = (const float*)d_in[15];
    float* out = (float*)d_out;

    float *h, *c, *h0, *c0, *hA, *cA, *hB, *cB, *Wsum;
    cudaGetSymbolAddress((void**)&h,    g_h);
    cudaGetSymbolAddress((void**)&c,    g_c);
    cudaGetSymbolAddress((void**)&h0,   g_h0);
    cudaGetSymbolAddress((void**)&c0,   g_c0);
    cudaGetSymbolAddress((void**)&hA,   g_hA);
    cudaGetSymbolAddress((void**)&cA,   g_cA);
    cudaGetSymbolAddress((void**)&hB,   g_hB);
    cudaGetSymbolAddress((void**)&cB,   g_cB);
    cudaGetSymbolAddress((void**)&Wsum, g_Wsum);

    // Initial hidden state = 0
    cudaMemsetAsync(h, 0, BB * DD * sizeof(float));
    cudaMemsetAsync(c, 0, BB * DD * sizeof(float));

    // Wsum = enc_W1 + enc_U1
    {
        int n = DD * NG;
        add_mats_kernel<<<(n + 255) / 256, 256>>>(enc_W1, enc_U1, Wsum, n);
    }

    const int ldt = TT * FF;   // row stride when indexing a (B,T,F) tensor's time slice

    // ---------------- Encoder: 128 steps, 2 layers ----------------
    for (int t = 0; t < TT; ++t) {
        // layer 0: z = x_t@W0 + h@U0 + b0
        lstm_cell_kernel<<<128, 256>>>(enc_in + (size_t)t * FF, ldt, FF, enc_W0,
                                       h, enc_U0, DD,
                                       enc_b0, c, h0, c0);
        // layer 1: x == h == h0  =>  z = h0@(W1+U1) + b1
        lstm_cell_kernel<<<128, 256>>>(h0, DD, DD, Wsum,
                                       (const float*)nullptr, (const float*)nullptr, 0,
                                       enc_b1, c0, h, c);
    }

    // ---------------- Decoder: 128 steps, 2 layers + dense ----------------
    for (int t = 0; t < TT; ++t) {
        const float* hcur = (t == 0) ? h : ((t & 1) ? hA : hB);
        const float* ccur = (t == 0) ? c : ((t & 1) ? cA : cB);
        float* hnext = (t & 1) ? hB : hA;
        float* cnext = (t & 1) ? cB : cA;

        // input: previous dense output (stored at out[:, T-t, :]) or dec_in[:,0,:]
        const float* X = (t == 0) ? dec_in : (out + (size_t)(TT - t) * FF);

        // layer 0: reads OLD h,c; its c2 is discarded by the reference
        lstm_cell_kernel<<<128, 256>>>(X, ldt, FF, dec_W0,
                                       hcur, dec_U0, DD,
                                       dec_b0, ccur, h0, c0);
        // layer 1: x = layer0 h, but h,c = OLD carry (reference quirk)
        lstm_cell_kernel<<<128, 256>>>(h0, DD, DD, dec_W1,
                                       hcur, dec_U1, DD,
                                       dec_b1, ccur, hnext, cnext);
        // dense: out_t -> out[:, T-1-t, :]  (reference reverses outs)
        dense_kernel<<<128, 128>>>(hnext, dense_W, dense_b,
                                   out + (size_t)(TT - 1 - t) * FF);
    }
}

// round 5
// speedup vs baseline: 1.0947x; 1.0947x over previous
#include <cuda_runtime.h>
#include <math.h>

// Problem constants
#define BB 128      // batch
#define TT 128      // time steps
#define FF 128      // features
#define DD 512      // hidden
#define NG 2048     // 4*D
#define KC 32       // K-chunk

// Scratch (device globals — no allocation allowed)
__device__ float g_h [BB*DD];
__device__ float g_c [BB*DD];
__device__ float g_h0[BB*DD];
__device__ float g_c0[BB*DD];
__device__ float g_hA[BB*DD];
__device__ float g_cA[BB*DD];
__device__ float g_hB[BB*DD];
__device__ float g_cB[BB*DD];
__device__ float g_Wsum[DD*NG];

__device__ __forceinline__ float sigmoidf_(float x) { return 1.0f / (1.0f + expf(-x)); }

__device__ __forceinline__ unsigned smem_u32(const void* p) {
    return (unsigned)__cvta_generic_to_shared(p);
}

#define CP_ASYNC16(dst_u32, src_ptr) \
    asm volatile("cp.async.cg.shared.global [%0], [%1], 16;\n" :: "r"(dst_u32), "l"(src_ptr))
#define CP_COMMIT() asm volatile("cp.async.commit_group;\n" ::: "memory")
#define CP_WAIT1()  asm volatile("cp.async.wait_group 1;\n" ::: "memory")

// Wsum = enc_W1 + enc_U1  (valid because encoder layer 1 has x == h)
__global__ void add_mats_kernel(const float* __restrict__ a, const float* __restrict__ b,
                                float* __restrict__ o, int n) {
    int i = blockIdx.x * blockDim.x + threadIdx.x;
    if (i < n) o[i] = a[i] + b[i];
}

// Fused LSTM cell: z = X@W (K1 cols, row stride ldx) + H@U (K2 cols) + bias,
// then i,f,o = sigmoid; g = relu; c2 = f*cin + i*g; h2 = o*relu(c2).
//
// Grid: 128 blocks; block owns 4 D-columns (all 4 gates => 16 z-cols, 2048 outputs).
// 512 threads: thread (r = tid>>2, g = tid&3) computes z[r][gate g][cols jb..jb+3] (4 accs).
// cp.async double-buffered pipeline: chunk k+1 loads overlap chunk k FFMAs.
// Epilogue: 8KB smem transpose brings all 4 gates of one (row,col) into one thread.
__global__ __launch_bounds__(512, 1) void lstm_cell_kernel(
    const float* __restrict__ X, int ldx, int K1, const float* __restrict__ W,
    const float* __restrict__ H, const float* __restrict__ U, int K2,
    const float* __restrict__ bias, const float* __restrict__ cin,
    float* __restrict__ hout, float* __restrict__ cout)
{
    __shared__ __align__(16) float As[2][BB][KC + 4];   // 36 KB (padded stride 36)
    __shared__ __align__(16) float Bs[2][KC][16];       // 4 KB, [k][gate*4 + cc]

    const int tid = threadIdx.x;
    const int jb4 = blockIdx.x * 4;        // D-column base
    const int r   = tid >> 2;              // 0..127 (compute row)
    const int g   = tid & 3;               // gate (compute)

    // staging roles
    const int ar  = tid >> 3;              // A rows ar and ar+64
    const int akq = tid & 7;               // A 16B-chunk within the 32-k slab
    const int bkk = tid >> 2;              // B k-row (tid<128 only)

    const int totK = K1 + K2;
    const int nck  = totK / KC;

    // --- staging helper: one K-chunk (A: 128x32, B: 32x16) via cp.async ---
    auto stage = [&](int ck, int buf) {
        const int k0 = ck * KC;
        const float *Ap, *Bp; int lda, kA, kB;
        if (k0 < K1) { Ap = X; lda = ldx; kA = k0;      Bp = W; kB = k0;      }
        else         { Ap = H; lda = DD;  kA = k0 - K1; Bp = U; kB = k0 - K1; }
        {
            unsigned d0 = smem_u32(&As[buf][ar][akq * 4]);
            const float* s0 = Ap + (size_t)ar * lda + kA + akq * 4;
            CP_ASYNC16(d0, s0);
            unsigned d1 = smem_u32(&As[buf][64 + ar][akq * 4]);
            const float* s1 = Ap + (size_t)(64 + ar) * lda + kA + akq * 4;
            CP_ASYNC16(d1, s1);
        }
        if (tid < 128) {
            unsigned d = smem_u32(&Bs[buf][bkk][g * 4]);
            const float* s = Bp + (size_t)(kB + bkk) * NG + g * DD + jb4;
            CP_ASYNC16(d, s);
        }
    };

    float4 acc = make_float4(0.f, 0.f, 0.f, 0.f);

    stage(0, 0);
    CP_COMMIT();

    for (int ck = 0; ck < nck; ++ck) {
        const int buf = ck & 1;
        if (ck + 1 < nck) stage(ck + 1, buf ^ 1);
        CP_COMMIT();               // possibly empty group (groups complete in order)
        CP_WAIT1();                // chunk ck's data has landed
        __syncthreads();

        #pragma unroll
        for (int k4 = 0; k4 < KC / 4; ++k4) {
            float4 a  = *(const float4*)&As[buf][r][k4 * 4];
            float4 b0 = *(const float4*)&Bs[buf][k4 * 4 + 0][g * 4];
            float4 b1 = *(const float4*)&Bs[buf][k4 * 4 + 1][g * 4];
            float4 b2 = *(const float4*)&Bs[buf][k4 * 4 + 2][g * 4];
            float4 b3 = *(const float4*)&Bs[buf][k4 * 4 + 3][g * 4];
            acc.x += a.x * b0.x; acc.y += a.x * b0.y; acc.z += a.x * b0.z; acc.w += a.x * b0.w;
            acc.x += a.y * b1.x; acc.y += a.y * b1.y; acc.z += a.y * b1.z; acc.w += a.y * b1.w;
            acc.x += a.z * b2.x; acc.y += a.z * b2.y; acc.z += a.z * b2.z; acc.w += a.z * b2.w;
            acc.x += a.w * b3.x; acc.y += a.w * b3.y; acc.z += a.w * b3.z; acc.w += a.w * b3.w;
        }
        __syncthreads();           // buffer 'buf' may be overwritten next iteration
    }

    // --- gate transpose through smem: zs[r][gate][cc] ---
    float* zs = &As[0][0][0];      // 2048 floats, all compute reads are done
    *(float4*)&zs[(r * 4 + g) * 4] = acc;
    __syncthreads();

    const int er  = tid >> 2;      // epilogue row
    const int ec  = tid & 3;       // epilogue col within group
    const int col = jb4 + ec;

    float zi = zs[er * 16 + 0  + ec];
    float zf = zs[er * 16 + 4  + ec];
    float zg = zs[er * 16 + 8  + ec];
    float zo = zs[er * 16 + 12 + ec];

    float i  = sigmoidf_(zi + bias[col]);
    float f  = sigmoidf_(zf + bias[DD + col]);
    float gg = fmaxf(zg + bias[2 * DD + col], 0.f);
    float o  = sigmoidf_(zo + bias[3 * DD + col]);
    float c2 = f * cin[er * DD + col] + i * gg;
    cout[er * DD + col] = c2;
    hout[er * DD + col] = o * fmaxf(c2, 0.f);
}

// out[b, col] = H[b,:] @ Wd[:,col] + bd[col]; one block per batch row.
__global__ __launch_bounds__(128, 1) void dense_kernel(
    const float* __restrict__ H, const float* __restrict__ Wd,
    const float* __restrict__ bd, float* __restrict__ out)
{
    __shared__ float hs[DD];
    const int row = blockIdx.x;
    const int col = threadIdx.x;
    const float* h = H + (size_t)row * DD;
    #pragma unroll
    for (int k = col; k < DD; k += 128) hs[k] = h[k];
    __syncthreads();
    float a0 = 0.f, a1 = 0.f, a2 = 0.f, a3 = 0.f;
    #pragma unroll 4
    for (int k = 0; k < DD; k += 4) {
        a0 += hs[k + 0] * Wd[(size_t)(k + 0) * FF + col];
        a1 += hs[k + 1] * Wd[(size_t)(k + 1) * FF + col];
        a2 += hs[k + 2] * Wd[(size_t)(k + 2) * FF + col];
        a3 += hs[k + 3] * Wd[(size_t)(k + 3) * FF + col];
    }
    out[(size_t)row * TT * FF + col] = (a0 + a1) + (a2 + a3) + bd[col];
}

extern "C" void kernel_launch(void* const* d_in, const int* in_sizes, int n_in,
                              void* d_out, int out_size)
{
    const float* enc_in  = (const float*)d_in[0];
    const float* dec_in  = (const float*)d_in[1];
    const float* enc_W0  = (const float*)d_in[2];
    const float* enc_U0  = (const float*)d_in[3];
    const float* enc_b0  = (const float*)d_in[4];
    const float* enc_W1  = (const float*)d_in[5];
    const float* enc_U1  = (const float*)d_in[6];
    const float* enc_b1  = (const float*)d_in[7];
    const float* dec_W0  = (const float*)d_in[8];
    const float* dec_U0  = (const float*)d_in[9];
    const float* dec_b0  = (const float*)d_in[10];
    const float* dec_W1  = (const float*)d_in[11];
    const float* dec_U1  = (const float*)d_in[12];
    const float* dec_b1  = (const float*)d_in[13];
    const float* dense_W = (const float*)d_in[14];
    const float* dense_b = (const float*)d_in[15];
    float* out = (float*)d_out;

    float *h, *c, *h0, *c0, *hA, *cA, *hB, *cB, *Wsum;
    cudaGetSymbolAddress((void**)&h,    g_h);
    cudaGetSymbolAddress((void**)&c,    g_c);
    cudaGetSymbolAddress((void**)&h0,   g_h0);
    cudaGetSymbolAddress((void**)&c0,   g_c0);
    cudaGetSymbolAddress((void**)&hA,   g_hA);
    cudaGetSymbolAddress((void**)&cA,   g_cA);
    cudaGetSymbolAddress((void**)&hB,   g_hB);
    cudaGetSymbolAddress((void**)&cB,   g_cB);
    cudaGetSymbolAddress((void**)&Wsum, g_Wsum);

    // Initial hidden state = 0
    cudaMemsetAsync(h, 0, BB * DD * sizeof(float));
    cudaMemsetAsync(c, 0, BB * DD * sizeof(float));

    // Wsum = enc_W1 + enc_U1
    {
        int n = DD * NG;
        add_mats_kernel<<<(n + 255) / 256, 256>>>(enc_W1, enc_U1, Wsum, n);
    }

    const int ldt = TT * FF;   // row stride when indexing a (B,T,F) tensor's time slice

    // ---------------- Encoder: 128 steps, 2 layers ----------------
    for (int t = 0; t < TT; ++t) {
        // layer 0: z = x_t@W0 + h@U0 + b0
        lstm_cell_kernel<<<128, 512>>>(enc_in + (size_t)t * FF, ldt, FF, enc_W0,
                                       h, enc_U0, DD,
                                       enc_b0, c, h0, c0);
        // layer 1: x == h == h0  =>  z = h0@(W1+U1) + b1
        lstm_cell_kernel<<<128, 512>>>(h0, DD, DD, Wsum,
                                       (const float*)nullptr, (const float*)nullptr, 0,
                                       enc_b1, c0, h, c);
    }

    // ---------------- Decoder: 128 steps, 2 layers + dense ----------------
    for (int t = 0; t < TT; ++t) {
        const float* hcur = (t == 0) ? h : ((t & 1) ? hA : hB);
        const float* ccur = (t == 0) ? c : ((t & 1) ? cA : cB);
        float* hnext = (t & 1) ? hB : hA;
        float* cnext = (t & 1) ? cB : cA;

        // input: previous dense output (stored at out[:, T-t, :]) or dec_in[:,0,:]
        const float* X = (t == 0) ? dec_in : (out + (size_t)(TT - t) * FF);

        // layer 0: reads OLD h,c; its c2 is discarded by the reference
        lstm_cell_kernel<<<128, 512>>>(X, ldt, FF, dec_W0,
                                       hcur, dec_U0, DD,
                                       dec_b0, ccur, h0, c0);
        // layer 1: x = layer0 h, but h,c = OLD carry (reference quirk)
        lstm_cell_kernel<<<128, 512>>>(h0, DD, DD, dec_W1,
                                       hcur, dec_U1, DD,
                                       dec_b1, ccur, hnext, cnext);
        // dense: out_t -> out[:, T-1-t, :]  (reference reverses outs)
        dense_kernel<<<128, 128>>>(hnext, dense_W, dense_b,
                                   out + (size_t)(TT - 1 - t) * FF);
    }
}

// round 7
// speedup vs baseline: 1.9652x; 1.7952x over previous
#include <cuda_runtime.h>
#include <math.h>
#include <stdint.h>

// Problem constants
#define BB 128      // batch
#define TT 128      // time steps
#define FF 128      // features
#define DD 512      // hidden
#define NG 2048     // 4*D
#define KC 32       // K-chunk (elements)
#define NSTAGE 4

// padded strides (floats)
#define ALD 36      // A stage row stride (conflict-free fragment LDS)
#define BLD 36      // B stage row stride
#define A_ST (BB*ALD)          // 4608 floats
#define B_ST (32*BLD)          // 1152 floats
#define STAGE_FLOATS (A_ST + B_ST)              // 5760
#define SMEM_BYTES (NSTAGE*STAGE_FLOATS*4)      // 92160
#define ZLD 34      // epilogue z-tile row stride

// ---- scratch (device globals; no allocation allowed) ----
__device__ float g_h [BB*DD];
__device__ float g_c [BB*DD];
__device__ float g_h0[BB*DD];
__device__ float g_c0[BB*DD];
__device__ float g_hA[BB*DD];
__device__ float g_cA[BB*DD];
__device__ float g_hB[BB*DD];
__device__ float g_cB[BB*DD];
__device__ float g_Wsum[DD*NG];
// permuted+tf32-rounded weights: [n][k], n = d*4+gate
__device__ float g_pEW0[NG*FF];
__device__ float g_pEU0[NG*DD];
__device__ float g_pW1s[NG*DD];
__device__ float g_pDW0[NG*FF];
__device__ float g_pDU0[NG*DD];
__device__ float g_pDW1[NG*DD];
__device__ float g_pDU1[NG*DD];
// permuted biases
__device__ float g_pbE0[NG];
__device__ float g_pbE1[NG];
__device__ float g_pbD0[NG];
__device__ float g_pbD1[NG];
// tf32-rounded inputs
__device__ float g_encR[BB*TT*FF];
__device__ float g_x0R [BB*FF];
__device__ float g_xfb [BB*FF];

// ---- helpers ----
__device__ __forceinline__ float sigmoidf_(float x) { return 1.0f / (1.0f + expf(-x)); }

__device__ __forceinline__ float rna_tf32(float x) {
    unsigned u;
    asm("cvt.rna.tf32.f32 %0, %1;" : "=r"(u) : "f"(x));
    return __uint_as_float(u);
}

__device__ __forceinline__ unsigned smem_u32(const void* p) {
    return (unsigned)__cvta_generic_to_shared(p);
}

#define CP_ASYNC16(dst_u32, src_ptr) \
    asm volatile("cp.async.cg.shared.global [%0], [%1], 16;\n" :: "r"(dst_u32), "l"(src_ptr))
#define CP_COMMIT() asm volatile("cp.async.commit_group;\n" ::: "memory")
#define CP_WAIT2()  asm volatile("cp.async.wait_group 2;\n" ::: "memory")

// m16n8k8 tf32 HMMA (baseline PTX, works at compute_103 target)
__device__ __forceinline__ void mma_tf32(float* d,
    unsigned a0, unsigned a1, unsigned a2, unsigned a3, unsigned b0, unsigned b1)
{
    asm volatile(
        "mma.sync.aligned.m16n8k8.row.col.f32.tf32.tf32.f32 "
        "{%0,%1,%2,%3}, {%4,%5,%6,%7}, {%8,%9}, {%0,%1,%2,%3};"
        : "+f"(d[0]), "+f"(d[1]), "+f"(d[2]), "+f"(d[3])
        : "r"(a0), "r"(a1), "r"(a2), "r"(a3), "r"(b0), "r"(b1));
}

// ================= preprocessing kernels =================
__global__ void add_mats_kernel(const float* __restrict__ a, const float* __restrict__ b,
                                float* __restrict__ o, int n) {
    int i = blockIdx.x * blockDim.x + threadIdx.x;
    if (i < n) o[i] = a[i] + b[i];
}

__global__ void round_copy_kernel(const float* __restrict__ s, float* __restrict__ d, int n) {
    int i = blockIdx.x * blockDim.x + threadIdx.x;
    if (i < n) d[i] = rna_tf32(s[i]);
}

// dst[n*K + k] = rna(src[k*2048 + (n&3)*512 + (n>>2)])  (K = 1<<kshift)
__global__ void permute_mat_kernel(const float* __restrict__ src, float* __restrict__ dst,
                                   int K, int kshift) {
    int i = blockIdx.x * blockDim.x + threadIdx.x;
    if (i >= NG * K) return;
    int k = i & (K - 1);
    int n = i >> kshift;
    int g = n & 3, d = n >> 2;
    dst[i] = rna_tf32(src[(size_t)k * NG + g * DD + d]);
}

__global__ void permute_bias_kernel(const float* __restrict__ b, float* __restrict__ pb) {
    int n = blockIdx.x * blockDim.x + threadIdx.x;
    if (n < NG) pb[n] = b[(n & 3) * DD + (n >> 2)];
}

// dec_in[:,0,:] -> rounded compact [128][128]
__global__ void round_slice0_kernel(const float* __restrict__ dec_in, float* __restrict__ d) {
    int i = blockIdx.x * blockDim.x + threadIdx.x;
    if (i < BB * FF) {
        int b = i >> 7, f = i & 127;
        d[i] = rna_tf32(dec_in[(size_t)b * TT * FF + f]);
    }
}

// ================= tensor-core LSTM cell (mma.sync tf32) =================
// z[128 x 32] = X@BW^T (K1) + H@BU^T (K2) + pbias   (BW/BU are permuted [n][k])
// gates; hout = rna_tf32(o * relu(c2)); cout = c2 (exact fp32).
// grid 64 blocks x 256 thr; block nb -> N-cols [nb*32,+32) = D-cols [nb*8,+8) x 4 gates.
__global__ __launch_bounds__(256, 1)
void lstm_cell_mma(const float* __restrict__ X, int ldx, int K1,
                   const float* __restrict__ BW,
                   const float* __restrict__ H, const float* __restrict__ BU, int K2,
                   const float* __restrict__ pbias, const float* __restrict__ cin,
                   float* __restrict__ hout, float* __restrict__ cout)
{
    extern __shared__ __align__(16) float sm[];

    const int tid   = threadIdx.x;
    const int lane  = tid & 31;
    const int wid   = tid >> 5;
    const int gid   = lane >> 2;         // group id 0..7
    const int tidg  = lane & 3;          // thread-in-group 0..3
    const int warpM = wid & 3;           // m-rows base = warpM*32
    const int warpN = wid >> 2;          // n-cols base = warpN*16
    const int nb32  = blockIdx.x * 32;

    const int nck = (K1 + K2) / KC;

    // ---- staging: chunk ck -> stage s (cp.async) ----
    auto stage = [&](int ck, int s) {
        const int k0 = ck * KC;
        const float* Ap; int lda_, kA; const float* Bp; int kB, ldb;
        if (k0 < K1) { Ap = X; lda_ = ldx; kA = k0;      Bp = BW; kB = k0;      ldb = K1; }
        else         { Ap = H; lda_ = DD;  kA = k0 - K1; Bp = BU; kB = k0 - K1; ldb = K2; }
        float* As = sm + s * STAGE_FLOATS;
        float* Bs = As + A_ST;
        // A: 128 rows x 128B; thread: row = tid>>1, quads (tid&1)*4 + 0..3
        {
            const int row = tid >> 1, q0 = (tid & 1) * 4;
            const float* src = Ap + (size_t)row * lda_ + kA + q0 * 4;
            const unsigned dst = smem_u32(As + row * ALD + q0 * 4);
            #pragma unroll
            for (int j = 0; j < 4; ++j) CP_ASYNC16(dst + j * 16, src + j * 4);
        }
        // B: 32 rows x 128B; thread: row = tid>>3, quad tid&7
        {
            const int row = tid >> 3, q = tid & 7;
            const float* src = Bp + (size_t)(nb32 + row) * ldb + kB + q * 4;
            const unsigned dst = smem_u32(Bs + row * BLD + q * 4);
            CP_ASYNC16(dst, src + 0);
        }
    };

    float acc[2][2][4];
    #pragma unroll
    for (int mt = 0; mt < 2; ++mt)
        #pragma unroll
        for (int nt = 0; nt < 2; ++nt)
            #pragma unroll
            for (int e = 0; e < 4; ++e) acc[mt][nt][e] = 0.f;

    stage(0, 0); CP_COMMIT();
    stage(1, 1); CP_COMMIT();
    stage(2, 2); CP_COMMIT();

    for (int ck = 0; ck < nck; ++ck) {
        CP_WAIT2();            // chunk ck landed (groups complete in order)
        __syncthreads();

        const float* As = sm + (ck & 3) * STAGE_FLOATS;
        const float* Bs = As + A_ST;

        #pragma unroll
        for (int ks = 0; ks < 4; ++ks) {
            const int kb = ks * 8;
            unsigned a[2][4];
            #pragma unroll
            for (int mt = 0; mt < 2; ++mt) {
                const int rb = warpM * 32 + mt * 16;
                a[mt][0] = __float_as_uint(As[(rb + gid    ) * ALD + kb + tidg    ]);
                a[mt][1] = __float_as_uint(As[(rb + gid + 8) * ALD + kb + tidg    ]);
                a[mt][2] = __float_as_uint(As[(rb + gid    ) * ALD + kb + tidg + 4]);
                a[mt][3] = __float_as_uint(As[(rb + gid + 8) * ALD + kb + tidg + 4]);
            }
            unsigned b[2][2];
            #pragma unroll
            for (int nt = 0; nt < 2; ++nt) {
                const int nbase = warpN * 16 + nt * 8;
                b[nt][0] = __float_as_uint(Bs[(nbase + gid) * BLD + kb + tidg    ]);
                b[nt][1] = __float_as_uint(Bs[(nbase + gid) * BLD + kb + tidg + 4]);
            }
            #pragma unroll
            for (int mt = 0; mt < 2; ++mt)
                #pragma unroll
                for (int nt = 0; nt < 2; ++nt)
                    mma_tf32(acc[mt][nt], a[mt][0], a[mt][1], a[mt][2], a[mt][3],
                             b[nt][0], b[nt][1]);
        }
        __syncthreads();       // release buf before it gets restaged

        if (ck + 3 < nck) stage(ck + 3, (ck + 3) & 3);
        CP_COMMIT();           // one group per iteration (may be empty)
    }

    // ---- epilogue: fragments -> smem z-tile -> gates ----
    float* zs = sm;            // 128 x ZLD floats (all compute synced above)
    #pragma unroll
    for (int mt = 0; mt < 2; ++mt) {
        #pragma unroll
        for (int nt = 0; nt < 2; ++nt) {
            const int row0 = warpM * 32 + mt * 16 + gid;
            const int col0 = warpN * 16 + nt * 8 + 2 * tidg;
            zs[(row0    ) * ZLD + col0    ] = acc[mt][nt][0];
            zs[(row0    ) * ZLD + col0 + 1] = acc[mt][nt][1];
            zs[(row0 + 8) * ZLD + col0    ] = acc[mt][nt][2];
            zs[(row0 + 8) * ZLD + col0 + 1] = acc[mt][nt][3];
        }
    }
    __syncthreads();

    {
        const int r  = tid >> 1;            // batch row
        const int db = (tid & 1) * 4;       // local d base (0 or 4)
        #pragma unroll
        for (int d = 0; d < 4; ++d) {
            const int nl  = (db + d) * 4;   // local n = dlocal*4 + gate
            const int col = blockIdx.x * 8 + db + d;
            float zi = zs[r * ZLD + nl + 0] + pbias[nb32 + nl + 0];
            float zf = zs[r * ZLD + nl + 1] + pbias[nb32 + nl + 1];
            float zg = zs[r * ZLD + nl + 2] + pbias[nb32 + nl + 2];
            float zo = zs[r * ZLD + nl + 3] + pbias[nb32 + nl + 3];
            float i  = sigmoidf_(zi);
            float f  = sigmoidf_(zf);
            float g  = fmaxf(zg, 0.f);
            float o  = sigmoidf_(zo);
            float c2 = f * cin[r * DD + col] + i * g;
            cout[r * DD + col] = c2;
            hout[r * DD + col] = rna_tf32(o * fmaxf(c2, 0.f));
        }
    }
}

// ================= dense =================
// out[b,col] = H[b,:]@Wd[:,col] + bd[col]; exact to out, tf32-rounded to xfb.
__global__ __launch_bounds__(128, 1) void dense_kernel(
    const float* __restrict__ H, const float* __restrict__ Wd,
    const float* __restrict__ bd, float* __restrict__ out, float* __restrict__ xfb)
{
    __shared__ float hs[DD];
    const int row = blockIdx.x;
    const int col = threadIdx.x;
    const float* h = H + (size_t)row * DD;
    #pragma unroll
    for (int k = col; k < DD; k += 128) hs[k] = h[k];
    __syncthreads();
    float a0 = 0.f, a1 = 0.f, a2 = 0.f, a3 = 0.f;
    #pragma unroll 4
    for (int k = 0; k < DD; k += 4) {
        a0 += hs[k + 0] * Wd[(size_t)(k + 0) * FF + col];
        a1 += hs[k + 1] * Wd[(size_t)(k + 1) * FF + col];
        a2 += hs[k + 2] * Wd[(size_t)(k + 2) * FF + col];
        a3 += hs[k + 3] * Wd[(size_t)(k + 3) * FF + col];
    }
    float v = (a0 + a1) + (a2 + a3) + bd[col];
    out[(size_t)row * TT * FF + col] = v;
    xfb[row * FF + col] = rna_tf32(v);
}

extern "C" void kernel_launch(void* const* d_in, const int* in_sizes, int n_in,
                              void* d_out, int out_size)
{
    const float* enc_in  = (const float*)d_in[0];
    const float* dec_in  = (const float*)d_in[1];
    const float* enc_W0  = (const float*)d_in[2];
    const float* enc_U0  = (const float*)d_in[3];
    const float* enc_b0  = (const float*)d_in[4];
    const float* enc_W1  = (const float*)d_in[5];
    const float* enc_U1  = (const float*)d_in[6];
    const float* enc_b1  = (const float*)d_in[7];
    const float* dec_W0  = (const float*)d_in[8];
    const float* dec_U0  = (const float*)d_in[9];
    const float* dec_b0  = (const float*)d_in[10];
    const float* dec_W1  = (const float*)d_in[11];
    const float* dec_U1  = (const float*)d_in[12];
    const float* dec_b1  = (const float*)d_in[13];
    const float* dense_W = (const float*)d_in[14];
    const float* dense_b = (const float*)d_in[15];
    float* out = (float*)d_out;

    cudaFuncSetAttribute(lstm_cell_mma, cudaFuncAttributeMaxDynamicSharedMemorySize, SMEM_BYTES);

    float *h, *c, *h0, *c0, *hA, *cA, *hB, *cB, *Wsum;
    float *pEW0, *pEU0, *pW1s, *pDW0, *pDU0, *pDW1, *pDU1;
    float *pbE0, *pbE1, *pbD0, *pbD1, *encR, *x0R, *xfb;
    cudaGetSymbolAddress((void**)&h,    g_h);
    cudaGetSymbolAddress((void**)&c,    g_c);
    cudaGetSymbolAddress((void**)&h0,   g_h0);
    cudaGetSymbolAddress((void**)&c0,   g_c0);
    cudaGetSymbolAddress((void**)&hA,   g_hA);
    cudaGetSymbolAddress((void**)&cA,   g_cA);
    cudaGetSymbolAddress((void**)&hB,   g_hB);
    cudaGetSymbolAddress((void**)&cB,   g_cB);
    cudaGetSymbolAddress((void**)&Wsum, g_Wsum);
    cudaGetSymbolAddress((void**)&pEW0, g_pEW0);
    cudaGetSymbolAddress((void**)&pEU0, g_pEU0);
    cudaGetSymbolAddress((void**)&pW1s, g_pW1s);
    cudaGetSymbolAddress((void**)&pDW0, g_pDW0);
    cudaGetSymbolAddress((void**)&pDU0, g_pDU0);
    cudaGetSymbolAddress((void**)&pDW1, g_pDW1);
    cudaGetSymbolAddress((void**)&pDU1, g_pDU1);
    cudaGetSymbolAddress((void**)&pbE0, g_pbE0);
    cudaGetSymbolAddress((void**)&pbE1, g_pbE1);
    cudaGetSymbolAddress((void**)&pbD0, g_pbD0);
    cudaGetSymbolAddress((void**)&pbD1, g_pbD1);
    cudaGetSymbolAddress((void**)&encR, g_encR);
    cudaGetSymbolAddress((void**)&x0R,  g_x0R);
    cudaGetSymbolAddress((void**)&xfb,  g_xfb);

    // -------- preprocessing --------
    cudaMemsetAsync(h, 0, BB * DD * sizeof(float));
    cudaMemsetAsync(c, 0, BB * DD * sizeof(float));

    { int n = BB * TT * FF; round_copy_kernel<<<(n + 255) / 256, 256>>>(enc_in, encR, n); }
    round_slice0_kernel<<<(BB * FF + 255) / 256, 256>>>(dec_in, x0R);

    { int n = DD * NG; add_mats_kernel<<<(n + 255) / 256, 256>>>(enc_W1, enc_U1, Wsum, n); }

    permute_mat_kernel<<<(NG * FF + 255) / 256, 256>>>(enc_W0, pEW0, FF, 7);
    permute_mat_kernel<<<(NG * DD + 255) / 256, 256>>>(enc_U0, pEU0, DD, 9);
    permute_mat_kernel<<<(NG * DD + 255) / 256, 256>>>(Wsum,   pW1s, DD, 9);
    permute_mat_kernel<<<(NG * FF + 255) / 256, 256>>>(dec_W0, pDW0, FF, 7);
    permute_mat_kernel<<<(NG * DD + 255) / 256, 256>>>(dec_U0, pDU0, DD, 9);
    permute_mat_kernel<<<(NG * DD + 255) / 256, 256>>>(dec_W1, pDW1, DD, 9);
    permute_mat_kernel<<<(NG * DD + 255) / 256, 256>>>(dec_U1, pDU1, DD, 9);

    permute_bias_kernel<<<8, 256>>>(enc_b0, pbE0);
    permute_bias_kernel<<<8, 256>>>(enc_b1, pbE1);
    permute_bias_kernel<<<8, 256>>>(dec_b0, pbD0);
    permute_bias_kernel<<<8, 256>>>(dec_b1, pbD1);

    const int ldt = TT * FF;

    // ---------------- Encoder: 128 steps, 2 layers ----------------
    for (int t = 0; t < TT; ++t) {
        lstm_cell_mma<<<64, 256, SMEM_BYTES>>>(encR + (size_t)t * FF, ldt, FF, pEW0,
                                               h, pEU0, DD,
                                               pbE0, c, h0, c0);
        // layer 1: x == h == h0 => z = h0@(W1+U1)
        lstm_cell_mma<<<64, 256, SMEM_BYTES>>>(h0, DD, DD, pW1s,
                                               (const float*)nullptr, (const float*)nullptr, 0,
                                               pbE1, c0, h, c);
    }

    // ---------------- Decoder: 128 steps, 2 layers + dense ----------------
    for (int t = 0; t < TT; ++t) {
        const float* hcur = (t == 0) ? h : ((t & 1) ? hA : hB);
        const float* ccur = (t == 0) ? c : ((t & 1) ? cA : cB);
        float* hnext = (t & 1) ? hB : hA;
        float* cnext = (t & 1) ? cB : cA;

        const float* X = (t == 0) ? x0R : xfb;   // tf32-rounded feedback

        // layer 0: reads OLD h,c; its c2 is discarded by the reference
        lstm_cell_mma<<<64, 256, SMEM_BYTES>>>(X, FF, FF, pDW0,
                                               hcur, pDU0, DD,
                                               pbD0, ccur, h0, c0);
        // layer 1: x = layer0 h, h/c = OLD carry (reference quirk)
        lstm_cell_mma<<<64, 256, SMEM_BYTES>>>(h0, DD, DD, pDW1,
                                               hcur, pDU1, DD,
                                               pbD1, ccur, hnext, cnext);
        // dense: exact fp32 -> out[:, T-1-t, :]; rounded copy -> xfb
        dense_kernel<<<128, 128>>>(hnext, dense_W, dense_b,
                                   out + (size_t)(TT - 1 - t) * FF, xfb);
    }
}

// round 8
// speedup vs baseline: 3.1994x; 1.6280x over previous
#include <cuda_runtime.h>
#include <math.h>
#include <stdint.h>

// Problem constants
#define BB 128      // batch
#define TT 128      // time steps
#define FF 128      // features
#define DD 512      // hidden
#define NG 2048     // 4*D
#define KC 32       // K-chunk (elements)
#define NSTAGE 4

// block tile: M=64 (2 M-halves), N=32 (64 N-groups) -> grid 128
#define BM 64
#define BN 32

// padded strides (floats)
#define ALD 36      // A stage row stride (conflict-free fragment LDS)
#define BLD 36      // B stage row stride
#define A_ST (BM*ALD)                           // 2304 floats
#define B_ST (BN*BLD)                           // 1152 floats
#define STAGE_FLOATS (A_ST + B_ST)              // 3456
#define SMEM_BYTES (NSTAGE*STAGE_FLOATS*4)      // 55296
#define ZLD 34      // epilogue z-tile row stride

// ---- scratch (device globals; no allocation allowed) ----
__device__ float g_h [BB*DD];
__device__ float g_c [BB*DD];
__device__ float g_h0[BB*DD];
__device__ float g_c0[BB*DD];
__device__ float g_hA[BB*DD];
__device__ float g_cA[BB*DD];
__device__ float g_hB[BB*DD];
__device__ float g_cB[BB*DD];
__device__ float g_Wsum[DD*NG];
// permuted+tf32-rounded weights: [n][k], n = d*4+gate
__device__ float g_pEW0[NG*FF];
__device__ float g_pEU0[NG*DD];
__device__ float g_pW1s[NG*DD];
__device__ float g_pDW0[NG*FF];
__device__ float g_pDU0[NG*DD];
__device__ float g_pDW1[NG*DD];
__device__ float g_pDU1[NG*DD];
// permuted biases
__device__ float g_pbE0[NG];
__device__ float g_pbE1[NG];
__device__ float g_pbD0[NG];
__device__ float g_pbD1[NG];
// tf32-rounded inputs
__device__ float g_encR[BB*TT*FF];
__device__ float g_x0R [BB*FF];
__device__ float g_xfb [BB*FF];

// ---- helpers ----
__device__ __forceinline__ float sigmoidf_(float x) { return 1.0f / (1.0f + expf(-x)); }

__device__ __forceinline__ float rna_tf32(float x) {
    unsigned u;
    asm("cvt.rna.tf32.f32 %0, %1;" : "=r"(u) : "f"(x));
    return __uint_as_float(u);
}

__device__ __forceinline__ unsigned smem_u32(const void* p) {
    return (unsigned)__cvta_generic_to_shared(p);
}

#define CP_ASYNC16(dst_u32, src_ptr) \
    asm volatile("cp.async.cg.shared.global [%0], [%1], 16;\n" :: "r"(dst_u32), "l"(src_ptr))
#define CP_COMMIT() asm volatile("cp.async.commit_group;\n" ::: "memory")
#define CP_WAIT2()  asm volatile("cp.async.wait_group 2;\n" ::: "memory")

// m16n8k8 tf32 HMMA (baseline PTX, works at compute_103 target)
__device__ __forceinline__ void mma_tf32(float* d,
    unsigned a0, unsigned a1, unsigned a2, unsigned a3, unsigned b0, unsigned b1)
{
    asm volatile(
        "mma.sync.aligned.m16n8k8.row.col.f32.tf32.tf32.f32 "
        "{%0,%1,%2,%3}, {%4,%5,%6,%7}, {%8,%9}, {%0,%1,%2,%3};"
        : "+f"(d[0]), "+f"(d[1]), "+f"(d[2]), "+f"(d[3])
        : "r"(a0), "r"(a1), "r"(a2), "r"(a3), "r"(b0), "r"(b1));
}

// ================= preprocessing kernels =================
__global__ void add_mats_kernel(const float* __restrict__ a, const float* __restrict__ b,
                                float* __restrict__ o, int n) {
    int i = blockIdx.x * blockDim.x + threadIdx.x;
    if (i < n) o[i] = a[i] + b[i];
}

__global__ void round_copy_kernel(const float* __restrict__ s, float* __restrict__ d, int n) {
    int i = blockIdx.x * blockDim.x + threadIdx.x;
    if (i < n) d[i] = rna_tf32(s[i]);
}

// dst[n*K + k] = rna(src[k*2048 + (n&3)*512 + (n>>2)])  (K = 1<<kshift)
__global__ void permute_mat_kernel(const float* __restrict__ src, float* __restrict__ dst,
                                   int K, int kshift) {
    int i = blockIdx.x * blockDim.x + threadIdx.x;
    if (i >= NG * K) return;
    int k = i & (K - 1);
    int n = i >> kshift;
    int g = n & 3, d = n >> 2;
    dst[i] = rna_tf32(src[(size_t)k * NG + g * DD + d]);
}

__global__ void permute_bias_kernel(const float* __restrict__ b, float* __restrict__ pb) {
    int n = blockIdx.x * blockDim.x + threadIdx.x;
    if (n < NG) pb[n] = b[(n & 3) * DD + (n >> 2)];
}

// dec_in[:,0,:] -> rounded compact [128][128]
__global__ void round_slice0_kernel(const float* __restrict__ dec_in, float* __restrict__ d) {
    int i = blockIdx.x * blockDim.x + threadIdx.x;
    if (i < BB * FF) {
        int b = i >> 7, f = i & 127;
        d[i] = rna_tf32(dec_in[(size_t)b * TT * FF + f]);
    }
}

// ================= tensor-core LSTM cell (mma.sync tf32) =================
// z[128 x 2048] = X@BW^T (K1) + H@BU^T (K2) + pbias   (BW/BU permuted [n][k])
// grid 128 blocks = (2 M-halves) x (64 N-groups); block tile M=64, N=32.
// 256 thr = 8 warps as 4M x 2N; warp tile 16M x 16N (acc[2][4]).
__global__ __launch_bounds__(256, 1)
void lstm_cell_mma(const float* __restrict__ X, int ldx, int K1,
                   const float* __restrict__ BW,
                   const float* __restrict__ H, const float* __restrict__ BU, int K2,
                   const float* __restrict__ pbias, const float* __restrict__ cin,
                   float* __restrict__ hout, float* __restrict__ cout)
{
    extern __shared__ __align__(16) float sm[];

    const int tid   = threadIdx.x;
    const int lane  = tid & 31;
    const int wid   = tid >> 5;
    const int gid   = lane >> 2;         // group id 0..7
    const int tidg  = lane & 3;          // thread-in-group 0..3
    const int warpM = wid & 3;           // m-rows base = warpM*16
    const int warpN = wid >> 2;          // n-cols base = warpN*16
    const int mb    = blockIdx.x & 1;    // M-half
    const int nb    = blockIdx.x >> 1;   // N-group
    const int mbase = mb * BM;
    const int nb32  = nb * BN;

    const int nck = (K1 + K2) / KC;

    // ---- staging: chunk ck -> stage s (cp.async) ----
    auto stage = [&](int ck, int s) {
        const int k0 = ck * KC;
        const float* Ap; int lda_, kA; const float* Bp; int kB, ldb;
        if (k0 < K1) { Ap = X; lda_ = ldx; kA = k0;      Bp = BW; kB = k0;      ldb = K1; }
        else         { Ap = H; lda_ = DD;  kA = k0 - K1; Bp = BU; kB = k0 - K1; ldb = K2; }
        float* As = sm + s * STAGE_FLOATS;
        float* Bs = As + A_ST;
        // A: 64 rows x 128B; thread: row = tid>>2, quads (tid&3)*2 + {0,1}
        {
            const int row = tid >> 2, q0 = (tid & 3) * 2;
            const float* src = Ap + (size_t)(mbase + row) * lda_ + kA + q0 * 4;
            const unsigned dst = smem_u32(As + row * ALD + q0 * 4);
            CP_ASYNC16(dst,      src);
            CP_ASYNC16(dst + 16, src + 4);
        }
        // B: 32 rows x 128B; thread: row = tid>>3, quad tid&7
        {
            const int row = tid >> 3, q = tid & 7;
            const float* src = Bp + (size_t)(nb32 + row) * ldb + kB + q * 4;
            const unsigned dst = smem_u32(Bs + row * BLD + q * 4);
            CP_ASYNC16(dst, src);
        }
    };

    float acc[2][4];
    #pragma unroll
    for (int nt = 0; nt < 2; ++nt)
        #pragma unroll
        for (int e = 0; e < 4; ++e) acc[nt][e] = 0.f;

    stage(0, 0); CP_COMMIT();
    stage(1, 1); CP_COMMIT();
    stage(2, 2); CP_COMMIT();

    for (int ck = 0; ck < nck; ++ck) {
        CP_WAIT2();            // chunk ck landed (groups complete in order)
        __syncthreads();

        const float* As = sm + (ck & 3) * STAGE_FLOATS;
        const float* Bs = As + A_ST;

        #pragma unroll
        for (int ks = 0; ks < 4; ++ks) {
            const int kb = ks * 8;
            const int rb = warpM * 16;
            unsigned a0 = __float_as_uint(As[(rb + gid    ) * ALD + kb + tidg    ]);
            unsigned a1 = __float_as_uint(As[(rb + gid + 8) * ALD + kb + tidg    ]);
            unsigned a2 = __float_as_uint(As[(rb + gid    ) * ALD + kb + tidg + 4]);
            unsigned a3 = __float_as_uint(As[(rb + gid + 8) * ALD + kb + tidg + 4]);
            #pragma unroll
            for (int nt = 0; nt < 2; ++nt) {
                const int nbase = warpN * 16 + nt * 8;
                unsigned b0 = __float_as_uint(Bs[(nbase + gid) * BLD + kb + tidg    ]);
                unsigned b1 = __float_as_uint(Bs[(nbase + gid) * BLD + kb + tidg + 4]);
                mma_tf32(acc[nt], a0, a1, a2, a3, b0, b1);
            }
        }
        __syncthreads();       // release buf before it gets restaged

        if (ck + 3 < nck) stage(ck + 3, (ck + 3) & 3);
        CP_COMMIT();           // one group per iteration (may be empty)
    }

    // ---- epilogue: fragments -> smem z-tile (64 x ZLD) -> gates ----
    float* zs = sm;
    #pragma unroll
    for (int nt = 0; nt < 2; ++nt) {
        const int row0 = warpM * 16 + gid;
        const int col0 = warpN * 16 + nt * 8 + 2 * tidg;
        zs[(row0    ) * ZLD + col0    ] = acc[nt][0];
        zs[(row0    ) * ZLD + col0 + 1] = acc[nt][1];
        zs[(row0 + 8) * ZLD + col0    ] = acc[nt][2];
        zs[(row0 + 8) * ZLD + col0 + 1] = acc[nt][3];
    }
    __syncthreads();

    {
        const int rl = tid >> 2;            // local batch row 0..63
        const int r  = mbase + rl;          // global batch row
        const int db = (tid & 3) * 2;       // local d base (0,2,4,6)
        #pragma unroll
        for (int d = 0; d < 2; ++d) {
            const int nl  = (db + d) * 4;   // local n = dlocal*4 + gate
            const int col = nb * 8 + db + d;
            float zi = zs[rl * ZLD + nl + 0] + pbias[nb32 + nl + 0];
            float zf = zs[rl * ZLD + nl + 1] + pbias[nb32 + nl + 1];
            float zg = zs[rl * ZLD + nl + 2] + pbias[nb32 + nl + 2];
            float zo = zs[rl * ZLD + nl + 3] + pbias[nb32 + nl + 3];
            float i  = sigmoidf_(zi);
            float f  = sigmoidf_(zf);
            float g  = fmaxf(zg, 0.f);
            float o  = sigmoidf_(zo);
            float c2 = f * cin[r * DD + col] + i * g;
            cout[r * DD + col] = c2;
            hout[r * DD + col] = rna_tf32(o * fmaxf(c2, 0.f));
        }
    }
}

// ================= dense =================
// out[b,col] = H[b,:]@Wd[:,col] + bd[col]; exact to out, tf32-rounded to xfb.
__global__ __launch_bounds__(128, 1) void dense_kernel(
    const float* __restrict__ H, const float* __restrict__ Wd,
    const float* __restrict__ bd, float* __restrict__ out, float* __restrict__ xfb)
{
    __shared__ float hs[DD];
    const int row = blockIdx.x;
    const int col = threadIdx.x;
    const float* h = H + (size_t)row * DD;
    #pragma unroll
    for (int k = col; k < DD; k += 128) hs[k] = h[k];
    __syncthreads();
    float a0 = 0.f, a1 = 0.f, a2 = 0.f, a3 = 0.f;
    #pragma unroll 4
    for (int k = 0; k < DD; k += 4) {
        a0 += hs[k + 0] * Wd[(size_t)(k + 0) * FF + col];
        a1 += hs[k + 1] * Wd[(size_t)(k + 1) * FF + col];
        a2 += hs[k + 2] * Wd[(size_t)(k + 2) * FF + col];
        a3 += hs[k + 3] * Wd[(size_t)(k + 3) * FF + col];
    }
    float v = (a0 + a1) + (a2 + a3) + bd[col];
    out[(size_t)row * TT * FF + col] = v;
    xfb[row * FF + col] = rna_tf32(v);
}

extern "C" void kernel_launch(void* const* d_in, const int* in_sizes, int n_in,
                              void* d_out, int out_size)
{
    const float* enc_in  = (const float*)d_in[0];
    const float* dec_in  = (const float*)d_in[1];
    const float* enc_W0  = (const float*)d_in[2];
    const float* enc_U0  = (const float*)d_in[3];
    const float* enc_b0  = (const float*)d_in[4];
    const float* enc_W1  = (const float*)d_in[5];
    const float* enc_U1  = (const float*)d_in[6];
    const float* enc_b1  = (const float*)d_in[7];
    const float* dec_W0  = (const float*)d_in[8];
    const float* dec_U0  = (const float*)d_in[9];
    const float* dec_b0  = (const float*)d_in[10];
    const float* dec_W1  = (const float*)d_in[11];
    const float* dec_U1  = (const float*)d_in[12];
    const float* dec_b1  = (const float*)d_in[13];
    const float* dense_W = (const float*)d_in[14];
    const float* dense_b = (const float*)d_in[15];
    float* out = (float*)d_out;

    cudaFuncSetAttribute(lstm_cell_mma, cudaFuncAttributeMaxDynamicSharedMemorySize, SMEM_BYTES);

    float *h, *c, *h0, *c0, *hA, *cA, *hB, *cB, *Wsum;
    float *pEW0, *pEU0, *pW1s, *pDW0, *pDU0, *pDW1, *pDU1;
    float *pbE0, *pbE1, *pbD0, *pbD1, *encR, *x0R, *xfb;
    cudaGetSymbolAddress((void**)&h,    g_h);
    cudaGetSymbolAddress((void**)&c,    g_c);
    cudaGetSymbolAddress((void**)&h0,   g_h0);
    cudaGetSymbolAddress((void**)&c0,   g_c0);
    cudaGetSymbolAddress((void**)&hA,   g_hA);
    cudaGetSymbolAddress((void**)&cA,   g_cA);
    cudaGetSymbolAddress((void**)&hB,   g_hB);
    cudaGetSymbolAddress((void**)&cB,   g_cB);
    cudaGetSymbolAddress((void**)&Wsum, g_Wsum);
    cudaGetSymbolAddress((void**)&pEW0, g_pEW0);
    cudaGetSymbolAddress((void**)&pEU0, g_pEU0);
    cudaGetSymbolAddress((void**)&pW1s, g_pW1s);
    cudaGetSymbolAddress((void**)&pDW0, g_pDW0);
    cudaGetSymbolAddress((void**)&pDU0, g_pDU0);
    cudaGetSymbolAddress((void**)&pDW1, g_pDW1);
    cudaGetSymbolAddress((void**)&pDU1, g_pDU1);
    cudaGetSymbolAddress((void**)&pbE0, g_pbE0);
    cudaGetSymbolAddress((void**)&pbE1, g_pbE1);
    cudaGetSymbolAddress((void**)&pbD0, g_pbD0);
    cudaGetSymbolAddress((void**)&pbD1, g_pbD1);
    cudaGetSymbolAddress((void**)&encR, g_encR);
    cudaGetSymbolAddress((void**)&x0R,  g_x0R);
    cudaGetSymbolAddress((void**)&xfb,  g_xfb);

    // -------- preprocessing --------
    cudaMemsetAsync(h, 0, BB * DD * sizeof(float));
    cudaMemsetAsync(c, 0, BB * DD * sizeof(float));

    { int n = BB * TT * FF; round_copy_kernel<<<(n + 255) / 256, 256>>>(enc_in, encR, n); }
    round_slice0_kernel<<<(BB * FF + 255) / 256, 256>>>(dec_in, x0R);

    { int n = DD * NG; add_mats_kernel<<<(n + 255) / 256, 256>>>(enc_W1, enc_U1, Wsum, n); }

    permute_mat_kernel<<<(NG * FF + 255) / 256, 256>>>(enc_W0, pEW0, FF, 7);
    permute_mat_kernel<<<(NG * DD + 255) / 256, 256>>>(enc_U0, pEU0, DD, 9);
    permute_mat_kernel<<<(NG * DD + 255) / 256, 256>>>(Wsum,   pW1s, DD, 9);
    permute_mat_kernel<<<(NG * FF + 255) / 256, 256>>>(dec_W0, pDW0, FF, 7);
    permute_mat_kernel<<<(NG * DD + 255) / 256, 256>>>(dec_U0, pDU0, DD, 9);
    permute_mat_kernel<<<(NG * DD + 255) / 256, 256>>>(dec_W1, pDW1, DD, 9);
    permute_mat_kernel<<<(NG * DD + 255) / 256, 256>>>(dec_U1, pDU1, DD, 9);

    permute_bias_kernel<<<8, 256>>>(enc_b0, pbE0);
    permute_bias_kernel<<<8, 256>>>(enc_b1, pbE1);
    permute_bias_kernel<<<8, 256>>>(dec_b0, pbD0);
    permute_bias_kernel<<<8, 256>>>(dec_b1, pbD1);

    const int ldt = TT * FF;

    // ---------------- Encoder: 128 steps, 2 layers ----------------
    for (int t = 0; t < TT; ++t) {
        lstm_cell_mma<<<128, 256, SMEM_BYTES>>>(encR + (size_t)t * FF, ldt, FF, pEW0,
                                                h, pEU0, DD,
                                                pbE0, c, h0, c0);
        // layer 1: x == h == h0 => z = h0@(W1+U1)
        lstm_cell_mma<<<128, 256, SMEM_BYTES>>>(h0, DD, DD, pW1s,
                                                (const float*)nullptr, (const float*)nullptr, 0,
                                                pbE1, c0, h, c);
    }

    // ---------------- Decoder: 128 steps, 2 layers + dense ----------------
    for (int t = 0; t < TT; ++t) {
        const float* hcur = (t == 0) ? h : ((t & 1) ? hA : hB);
        const float* ccur = (t == 0) ? c : ((t & 1) ? cA : cB);
        float* hnext = (t & 1) ? hB : hA;
        float* cnext = (t & 1) ? cB : cA;

        const float* X = (t == 0) ? x0R : xfb;   // tf32-rounded feedback

        // layer 0: reads OLD h,c; its c2 is discarded by the reference
        lstm_cell_mma<<<128, 256, SMEM_BYTES>>>(X, FF, FF, pDW0,
                                                hcur, pDU0, DD,
                                                pbD0, ccur, h0, c0);
        // layer 1: x = layer0 h, h/c = OLD carry (reference quirk)
        lstm_cell_mma<<<128, 256, SMEM_BYTES>>>(h0, DD, DD, pDW1,
                                                hcur, pDU1, DD,
                                                pbD1, ccur, hnext, cnext);
        // dense: exact fp32 -> out[:, T-1-t, :]; rounded copy -> xfb
        dense_kernel<<<128, 128>>>(hnext, dense_W, dense_b,
                                   out + (size_t)(TT - 1 - t) * FF, xfb);
    }
}